// round 4
// baseline (speedup 1.0000x reference)
#include <cuda_runtime.h>

// ConstituencyMFVI: B=8, N=192, 3 iterations.
// 2-CTA cluster per (b,i): rows j>i split in half across the pair.
// Each CTA: <=96 rows in SMEM (78.3KB) -> 2 CTAs resident per SM.
// sig exchanged across the pair via double-buffered DSMEM + barrier.cluster.
// cp.async chunked load fused with iteration 1 (weights = sigmoid(span)).

#define NDIM    192
#define RPAD    196      // row pad: 16B-aligned, conflict-free column LDS.128
#define MAXR    96
#define NF4ROW  48
#define THREADS 384

static const int SP_FLOATS  = MAXR * RPAD;                            // 18816
static const int SMEM_BYTES = (SP_FLOATS + 2 * NDIM + THREADS) * 4;   // 78336

__device__ __forceinline__ unsigned smem_u32(const void* p) {
    return (unsigned)__cvta_generic_to_shared(p);
}
__device__ __forceinline__ float sigmoidf_(float x) {
    return 1.0f / (1.0f + __expf(-x));
}
__device__ __forceinline__ void cluster_sync_() {
    asm volatile("barrier.cluster.arrive.aligned;" ::: "memory");
    asm volatile("barrier.cluster.wait.aligned;" ::: "memory");
}

__global__ void __launch_bounds__(THREADS, 2) __cluster_dims__(2, 1, 1)
mfvi_kernel(const float* __restrict__ s_span,
            const float* __restrict__ s_pair,
            float* __restrict__ out)
{
    extern __shared__ float smem[];
    float* sp      = smem;                    // [MAXR][RPAD] own rows
    float* sigbuf  = smem + SP_FLOATS;        // [2][NDIM] double-buffered sig
    float* partial = sigbuf + 2 * NDIM;       // [THREADS]

    const int h   = blockIdx.x & 1;           // cluster rank
    const int bi  = blockIdx.x >> 1;          // b*192 + i
    const int i   = bi % NDIM;
    const int tid = threadIdx.x;
    const int lr  = tid % MAXR;               // local row index
    const int qd  = tid / MAXR;               // k-quarter: [48*qd, 48*qd+48)

    const int rowStart = i + 1;
    const int nRows    = NDIM - rowStart;
    const int half0    = (nRows + 1) >> 1;
    const int ja       = h ? (rowStart + half0) : rowStart;
    const int nLocal   = h ? (NDIM - ja) : half0;

    // ---- cp.async loads of own rows, 4 commit groups ----
    const float* gbase = s_pair + (size_t)bi * (NDIM * NDIM);
    const int rpc = (nLocal + 3) >> 2;
    #pragma unroll
    for (int c = 0; c < 4; ++c) {
        int ra = c * rpc;   if (ra > nLocal) ra = nLocal;
        int rb = ra + rpc;  if (rb > nLocal) rb = nLocal;
        for (int idx = ra * NF4ROW + tid; idx < rb * NF4ROW; idx += THREADS) {
            int r   = idx / NF4ROW;
            int col = (idx % NF4ROW) * 4;
            const float* src = gbase + (size_t)(ja + r) * NDIM + col;
            unsigned dst = smem_u32(sp + r * RPAD + col);
            asm volatile("cp.async.cg.shared.global [%0], [%1], 16;"
                         :: "r"(dst), "l"(src));
        }
        asm volatile("cp.async.commit_group;");
    }

    // ---- sig0 = sigmoid(span) for all j (local, no exchange needed) ----
    float s0 = 0.5f;
    if (tid < NDIM) {
        float sv = s_span[(size_t)bi * NDIM + tid];
        s0 = sigmoidf_(sv);
        sigbuf[tid] = s0;                     // buf0
    }
    float span_own = 0.0f;
    if (tid < MAXR && tid < nLocal)
        span_own = s_span[(size_t)bi * NDIM + (ja + tid)];
    __syncthreads();

    const float4* sigA4 = reinterpret_cast<const float4*>(sigbuf)        + qd * 12;
    const float4* sigB4 = reinterpret_cast<const float4*>(sigbuf + NDIM) + qd * 12;
    const float4* row4  = reinterpret_cast<const float4*>(sp + lr * RPAD + qd * 48);

    // ---- Iteration 1, fused with chunk arrival ----
    float a0 = 0.f, a1 = 0.f, a2 = 0.f, a3 = 0.f;
    #pragma unroll
    for (int c = 0; c < 4; ++c) {
        int ra = c * rpc;   if (ra > nLocal) ra = nLocal;
        int rb = ra + rpc;  if (rb > nLocal) rb = nLocal;
        if      (c == 0) asm volatile("cp.async.wait_group 3;");
        else if (c == 1) asm volatile("cp.async.wait_group 2;");
        else if (c == 2) asm volatile("cp.async.wait_group 1;");
        else             asm volatile("cp.async.wait_group 0;");
        __syncthreads();
        int nz = 2 * (rb - ra);
        for (int z = tid; z < nz; z += THREADS) {
            int r = ra + (z >> 1);
            sp[r * RPAD + ((z & 1) ? i : (ja + r))] = 0.0f;  // mask k==i,k==j
        }
        __syncthreads();
        if (lr >= ra && lr < rb) {
            #pragma unroll
            for (int u = 0; u < 12; ++u) {
                float4 v = row4[u]; float4 s = sigA4[u];
                a0 += v.x * s.x; a1 += v.y * s.y;
                a2 += v.z * s.z; a3 += v.w * s.w;
            }
        }
    }
    partial[tid] = (a0 + a1) + (a2 + a3);
    __syncthreads();

    // combine -> q, sig; publish own-row sig into buf1 (local + peer DSMEM)
    float q_own = 0.0f;
    if (tid < MAXR && tid < nLocal) {
        q_own = span_own + partial[tid] + partial[tid + 96]
                         + partial[tid + 192] + partial[tid + 288];
        float sg = sigmoidf_(q_own);
        int j = ja + tid;
        sigbuf[NDIM + j] = sg;
        unsigned la = smem_u32(&sigbuf[NDIM + j]);
        unsigned ra_;
        asm volatile("mapa.shared::cluster.u32 %0, %1, %2;"
                     : "=r"(ra_) : "r"(la), "r"(h ^ 1));
        asm volatile("st.shared::cluster.f32 [%0], %1;" :: "r"(ra_), "f"(sg));
    }
    if (tid <= i) sigbuf[NDIM + tid] = s0;    // constant rows of buf1
    cluster_sync_();

    // ---- Iteration 2 (reads buf1, writes buf0) ----
    {
        float d0 = 0.f, d1 = 0.f, d2 = 0.f, d3 = 0.f;
        if (lr < nLocal) {
            #pragma unroll
            for (int u = 0; u < 12; ++u) {
                float4 v = row4[u]; float4 s = sigB4[u];
                d0 += v.x * s.x; d1 += v.y * s.y;
                d2 += v.z * s.z; d3 += v.w * s.w;
            }
        }
        partial[tid] = (d0 + d1) + (d2 + d3);
        __syncthreads();
        if (tid < MAXR && tid < nLocal) {
            q_own = span_own + partial[tid] + partial[tid + 96]
                             + partial[tid + 192] + partial[tid + 288];
            float sg = sigmoidf_(q_own);
            int j = ja + tid;
            sigbuf[j] = sg;                   // buf0 (j<=i entries already s0)
            unsigned la = smem_u32(&sigbuf[j]);
            unsigned ra_;
            asm volatile("mapa.shared::cluster.u32 %0, %1, %2;"
                         : "=r"(ra_) : "r"(la), "r"(h ^ 1));
            asm volatile("st.shared::cluster.f32 [%0], %1;" :: "r"(ra_), "f"(sg));
        }
        cluster_sync_();
    }

    // ---- Iteration 3 (reads buf0) + output ----
    {
        float d0 = 0.f, d1 = 0.f, d2 = 0.f, d3 = 0.f;
        if (lr < nLocal) {
            #pragma unroll
            for (int u = 0; u < 12; ++u) {
                float4 v = row4[u]; float4 s = sigA4[u];
                d0 += v.x * s.x; d1 += v.y * s.y;
                d2 += v.z * s.z; d3 += v.w * s.w;
            }
        }
        partial[tid] = (d0 + d1) + (d2 + d3);
        __syncthreads();
        if (tid < MAXR && tid < nLocal) {
            q_own = span_own + partial[tid] + partial[tid + 96]
                             + partial[tid + 192] + partial[tid + 288];
            out[(size_t)bi * NDIM + (ja + tid)] = sigmoidf_(q_own);
        }
    }
    if (h == 0 && tid <= i)                   // rows j<=i: q stays = span
        out[(size_t)bi * NDIM + tid] = s0;
}

extern "C" void kernel_launch(void* const* d_in, const int* in_sizes, int n_in,
                              void* d_out, int out_size)
{
    (void)in_sizes; (void)n_in; (void)out_size;
    const float* s_span = (const float*)d_in[0];
    const float* s_pair = (const float*)d_in[1];
    float* out = (float*)d_out;

    cudaFuncSetAttribute(mfvi_kernel,
                         cudaFuncAttributeMaxDynamicSharedMemorySize, SMEM_BYTES);

    const int grid = 2 * 8 * NDIM;   // 2 CTAs (cluster) per (b,i) = 3072
    mfvi_kernel<<<grid, THREADS, SMEM_BYTES>>>(s_span, s_pair, out);
}

// round 5
// speedup vs baseline: 1.4963x; 1.4963x over previous
#include <cuda_runtime.h>

// ConstituencyMFVI: B=8, N=192, 3 iterations.
// One INDEPENDENT CTA per (b,i); no inter-CTA coupling (R4 cluster lesson).
// First 140 rows of the tile cached in SMEM (110.9KB -> 2 CTAs/SM);
// overflow rows (only when i<51) are dotted from gmem/L2 each iteration.
// Masked terms k==i, k==j handled by analytic corrections (no zero passes).
// sig double-buffered: 2 barriers per iteration.
// cp.async chunked load fused with iteration 1 (weights = sigmoid(span)).

#define NDIM    192
#define RPAD    196     // 16B-aligned rows, conflict-free column LDS.128
#define SROWS   140     // rows cached in SMEM
#define NF4ROW  48
#define THREADS 384

static const int SP_FLOATS  = SROWS * RPAD;                           // 27440
static const int SMEM_BYTES = (SP_FLOATS + 2 * NDIM + THREADS) * 4;   // 112832

__device__ __forceinline__ unsigned smem_u32(const void* p) {
    return (unsigned)__cvta_generic_to_shared(p);
}
__device__ __forceinline__ float sigmoidf_(float x) {
    return 1.0f / (1.0f + __expf(-x));
}

// 96-element half-row dot with 4-way ILP + masked-term corrections.
template <typename RowPtr>
__device__ __forceinline__ float half_dot(const RowPtr row,        // full 192-row base
                                          const float* __restrict__ sg,  // sig[192]
                                          int h, int i, int jj)
{
    float a0 = 0.f, a1 = 0.f, a2 = 0.f, a3 = 0.f;
    const int base = h * 96;
    #pragma unroll
    for (int u = 0; u < 24; ++u) {
        float4 v = *reinterpret_cast<const float4*>(row + base + 4 * u);
        float4 s = *reinterpret_cast<const float4*>(sg  + base + 4 * u);
        a0 += v.x * s.x; a1 += v.y * s.y; a2 += v.z * s.z; a3 += v.w * s.w;
    }
    float acc = (a0 + a1) + (a2 + a3);
    if ((i  >> 6 >> 1) + ((i  >= 96) ? 0 : 0), (i >= base && i < base + 96))
        acc -= sg[i] * row[i];
    if (jj >= base && jj < base + 96)
        acc -= sg[jj] * row[jj];
    return acc;
}

__global__ void __launch_bounds__(THREADS, 2)
mfvi_kernel(const float* __restrict__ s_span,
            const float* __restrict__ s_pair,
            float* __restrict__ out)
{
    extern __shared__ float smem[];
    float* sp      = smem;                    // [SROWS][RPAD]
    float* sigA    = smem + SP_FLOATS;        // [NDIM]
    float* sigB    = sigA + NDIM;             // [NDIM]
    float* partial = sigB + NDIM;             // [THREADS]

    const int bi  = blockIdx.x;               // b*192 + i
    const int i   = bi % NDIM;
    const int tid = threadIdx.x;
    const int jj  = tid % NDIM;               // row handled by this thread
    const int h   = tid / NDIM;               // k-half: [96h, 96h+96)

    const int rowStart = i + 1;
    const int nRows    = NDIM - rowStart;
    const int nS       = (nRows < SROWS) ? nRows : SROWS;
    const int rpc      = (nS + 3) >> 2;

    const float* gbase = s_pair + (size_t)bi * (NDIM * NDIM);

    // ---- cp.async loads of SMEM rows, 4 commit groups ----
    #pragma unroll
    for (int c = 0; c < 4; ++c) {
        int ra = c * rpc;   if (ra > nS) ra = nS;
        int rb = ra + rpc;  if (rb > nS) rb = nS;
        for (int idx = ra * NF4ROW + tid; idx < rb * NF4ROW; idx += THREADS) {
            int r   = idx / NF4ROW;
            int col = (idx % NF4ROW) * 4;
            const float* src = gbase + (size_t)(rowStart + r) * NDIM + col;
            unsigned dst = smem_u32(sp + r * RPAD + col);
            asm volatile("cp.async.cg.shared.global [%0], [%1], 16;"
                         :: "r"(dst), "l"(src));
        }
        asm volatile("cp.async.commit_group;");
    }

    // ---- sig0 = sigmoid(span) ----
    float s0 = 0.5f, span_j = 0.0f;
    if (tid < NDIM) {
        span_j = s_span[(size_t)bi * NDIM + tid];
        s0 = sigmoidf_(span_j);
        sigA[tid] = s0;
    }
    __syncthreads();

    const int  r      = jj - rowStart;                 // smem row index
    const bool active = (jj > i);
    const bool inSmem = active && (r < nS);
    const float* grow = gbase + (size_t)jj * NDIM;     // gmem row (overflow)
    const float* srow = sp + (size_t)r * RPAD;

    // ---- Iteration 1, fused with chunk arrival ----
    float acc = 0.0f;
    if (active && !inSmem)                   // overflow rows: gmem dot now
        acc = half_dot(grow, sigA, h, i, jj);

    #pragma unroll
    for (int c = 0; c < 4; ++c) {
        if      (c == 0) asm volatile("cp.async.wait_group 3;");
        else if (c == 1) asm volatile("cp.async.wait_group 2;");
        else if (c == 2) asm volatile("cp.async.wait_group 1;");
        else             asm volatile("cp.async.wait_group 0;");
        __syncthreads();
        int ra = c * rpc;   if (ra > nS) ra = nS;
        int rb = ra + rpc;  if (rb > nS) rb = nS;
        if (inSmem && r >= ra && r < rb)
            acc = half_dot(srow, sigA, h, i, jj);
    }
    partial[tid] = acc;
    __syncthreads();
    if (tid < NDIM) {
        float sg = s0;
        if (tid > i) {
            float q = span_j + partial[tid] + partial[tid + NDIM];
            sg = sigmoidf_(q);
        }
        sigB[tid] = sg;
    }
    __syncthreads();

    // ---- Iteration 2 (reads sigB, writes sigA) ----
    acc = 0.0f;
    if (inSmem)            acc = half_dot(srow, sigB, h, i, jj);
    else if (active)       acc = half_dot(grow, sigB, h, i, jj);
    partial[tid] = acc;
    __syncthreads();
    if (tid < NDIM) {
        float sg = s0;
        if (tid > i) {
            float q = span_j + partial[tid] + partial[tid + NDIM];
            sg = sigmoidf_(q);
        }
        sigA[tid] = sg;
    }
    __syncthreads();

    // ---- Iteration 3 (reads sigA) + output ----
    acc = 0.0f;
    if (inSmem)            acc = half_dot(srow, sigA, h, i, jj);
    else if (active)       acc = half_dot(grow, sigA, h, i, jj);
    partial[tid] = acc;
    __syncthreads();
    if (tid < NDIM) {
        float o = s0;                         // rows j<=i: q stays = span
        if (tid > i) {
            float q = span_j + partial[tid] + partial[tid + NDIM];
            o = sigmoidf_(q);
        }
        out[(size_t)bi * NDIM + tid] = o;
    }
}

extern "C" void kernel_launch(void* const* d_in, const int* in_sizes, int n_in,
                              void* d_out, int out_size)
{
    (void)in_sizes; (void)n_in; (void)out_size;
    const float* s_span = (const float*)d_in[0];
    const float* s_pair = (const float*)d_in[1];
    // d_in[2] = mask: analytic (strict upper triangle), not needed.
    float* out = (float*)d_out;

    cudaFuncSetAttribute(mfvi_kernel,
                         cudaFuncAttributeMaxDynamicSharedMemorySize, SMEM_BYTES);

    const int grid = 8 * NDIM;   // one CTA per (b,i) = 1536
    mfvi_kernel<<<grid, THREADS, SMEM_BYTES>>>(s_span, s_pair, out);
}